// round 16
// baseline (speedup 1.0000x reference)
#include <cuda_runtime.h>
#include <cuda_bf16.h>
#include <cstdint>

// SeparationLoss: mean over B of sum_{i!=j} max(0, thr2 - ||kp_i - kp_j||^2)
// Input: batched_kps [B, 17, 3] f32 (B = 131072). Output: scalar f32.
//
// R16 (consolidation): wall is pinned at the 12.768us harness floor (4
// different kernels measured identical to the ns), so optimize the other
// axes: diff-form pair math for max accuracy (rel_err ~7e-8 vs 1.4e-5 Gram),
// R13's static 2-tile pipeline for best cold-cache time (both bulk copies at
// t=0, tile-B copy hides under tile-A compute), grid 512 = one wave, fused
// last-block-done reduction.

#define J 17
#define ROW_F 51                    // 17*3 floats per row
#define TILE_ROWS 128
#define THREADS 128
#define TILE_BYTES (TILE_ROWS * ROW_F * 4)    // 26112
#define NBLOCKS_MAX 8192

__device__ __align__(16) float g_partials[NBLOCKS_MAX];
__device__ unsigned int g_done_count;   // zero-init; inc wraps -> self-resets per run

__device__ __forceinline__ uint32_t smem_u32(const void* p) {
    uint32_t a;
    asm("{ .reg .u64 t; cvta.to.shared.u64 t, %1; cvt.u32.u64 %0, t; }"
        : "=r"(a) : "l"(p));
    return a;
}

__device__ __forceinline__ void mbar_wait0(uint32_t mb) {
    uint32_t done;
    asm volatile(
        "{\n\t.reg .pred p;\n\t"
        "mbarrier.try_wait.parity.acquire.cta.shared::cta.b64 p, [%1], 0;\n\t"
        "selp.b32 %0, 1, 0, p;\n\t}"
        : "=r"(done) : "r"(mb) : "memory");
    if (!done) {
        asm volatile(
            "{\n\t.reg .pred P1;\n\t"
            "W_%=:\n\t"
            "mbarrier.try_wait.parity.acquire.cta.shared::cta.b64 P1, [%0], 0, 0x989680;\n\t"
            "@P1 bra.uni D_%=;\n\t"
            "bra.uni W_%=;\n\t"
            "D_%=:\n\t}"
            :: "r"(mb) : "memory");
    }
}

__device__ __forceinline__ void issue_bulk(uint32_t mb, uint32_t dst,
                                           const float* gsrc) {
    asm volatile("mbarrier.arrive.expect_tx.shared.b64 _, [%0], %1;"
                 :: "r"(mb), "r"((uint32_t)TILE_BYTES) : "memory");
    asm volatile(
        "cp.async.bulk.shared::cta.global.mbarrier::complete_tx::bytes "
        "[%0], [%1], %2, [%3];"
        :: "r"(dst), "l"(gsrc), "r"((uint32_t)TILE_BYTES), "r"(mb)
        : "memory");
}

// Diff-form pair sum for one row (most accurate: no cancellation identity).
// hinge contribution = max(0, -(d2 - thr2)); caller scales by 2 for ordered pairs.
__device__ __forceinline__ void row_pairs(const float* __restrict__ rp,
                                          float& a0, float& a1) {
    float p[ROW_F];
    #pragma unroll
    for (int c = 0; c < ROW_F; c++) p[c] = rp[c];

    const float thr2 = 0.01f;   // THRESHOLD^2
    int k = 0;
    #pragma unroll
    for (int i = 0; i < J; i++) {
        #pragma unroll
        for (int j = i + 1; j < J; j++) {
            float dx = p[3*i + 0] - p[3*j + 0];
            float dy = p[3*i + 1] - p[3*j + 1];
            float dz = p[3*i + 2] - p[3*j + 2];
            float t  = fmaf(dx, dx, fmaf(dy, dy, fmaf(dz, dz, -thr2)));
            float h  = fmaxf(-t, 0.0f);      // FMNMX w/ neg modifier (alu pipe)
            if (k & 1) a1 += h; else a0 += h;
            k++;
        }
    }
}

__global__ __launch_bounds__(THREADS, 4)   // smem-limited to 4/SM; 128-reg cap
void sep_loss_fused(const float* __restrict__ kps, int B, int grid,
                    float invB, float* __restrict__ out) {
    __shared__ __align__(16) float sA[TILE_ROWS * ROW_F];   // 26112 B
    __shared__ __align__(16) float sB[TILE_ROWS * ROW_F];   // 26112 B
    __shared__ __align__(8)  unsigned long long mbarA, mbarB;
    __shared__ float wsum[THREADS / 32];
    __shared__ bool  isLast;

    const int tid = threadIdx.x;
    const int blk = blockIdx.x;
    const int rowBaseA = blk * TILE_ROWS;                 // tile A: blk
    const int rowBaseB = (blk + grid) * TILE_ROWS;        // tile B: blk + grid
    const int rowsA = min(TILE_ROWS, max(0, B - rowBaseA));
    const int rowsB = min(TILE_ROWS, max(0, B - rowBaseB));
    const uint32_t mbA = smem_u32(&mbarA), mbB = smem_u32(&mbarB);

    if (tid == 0) {
        asm volatile("mbarrier.init.shared.b64 [%0], 1;" :: "r"(mbA) : "memory");
        asm volatile("mbarrier.init.shared.b64 [%0], 1;" :: "r"(mbB) : "memory");
    }
    __syncthreads();

    // ---- issue BOTH copies up front: tile-B copy overlaps tile-A compute ----
    if (tid == 0) {
        if (rowsA == TILE_ROWS)
            issue_bulk(mbA, smem_u32(sA), kps + (size_t)rowBaseA * ROW_F);
        if (rowsB == TILE_ROWS)
            issue_bulk(mbB, smem_u32(sB), kps + (size_t)rowBaseB * ROW_F);
    }

    float a0 = 0.0f, a1 = 0.0f;

    // ================= section A (static buffer sA) =================
    if (rowsA == TILE_ROWS) {
        mbar_wait0(mbA);
    } else if (rowsA > 0) {
        const float* src = kps + (size_t)rowBaseA * ROW_F;
        for (int i = tid; i < rowsA * ROW_F; i += THREADS) sA[i] = src[i];
        __syncthreads();
    }
    if (tid < rowsA) row_pairs(sA + tid * ROW_F, a0, a1);

    // ================= section B (static buffer sB) =================
    if (rowsB == TILE_ROWS) {
        mbar_wait0(mbB);
    } else if (rowsB > 0) {
        const float* src = kps + (size_t)rowBaseB * ROW_F;
        for (int i = tid; i < rowsB * ROW_F; i += THREADS) sB[i] = src[i];
        __syncthreads();
    }
    if (tid < rowsB) row_pairs(sB + tid * ROW_F, a0, a1);

    float acc = (a0 + a1) * 2.0f;            // ordered pairs

    // ---- deterministic block reduction (4 warps) ----
    #pragma unroll
    for (int off = 16; off > 0; off >>= 1)
        acc += __shfl_down_sync(0xFFFFFFFFu, acc, off);
    if ((tid & 31) == 0) wsum[tid >> 5] = acc;
    __syncthreads();

    if (tid == 0) {
        g_partials[blk] = (wsum[0] + wsum[1]) + (wsum[2] + wsum[3]);
        // release-inc orders the store; wraps to 0 at grid-1 (replay-safe)
        unsigned int c;
        asm volatile("atom.acq_rel.gpu.global.inc.u32 %0, [%1], %2;"
                     : "=r"(c)
                     : "l"(&g_done_count), "r"((unsigned int)(grid - 1))
                     : "memory");
        isLast = (c == (unsigned int)(grid - 1));
    }
    __syncthreads();

    // ---- last block: 512 partials = 1 float4 per thread ----
    if (isLast) {
        float v = 0.0f;
        const int nvec = grid >> 2;               // 128 for grid=512
        const float4* gp = reinterpret_cast<const float4*>(g_partials);
        for (int i = tid; i < nvec; i += THREADS) {
            float4 f = gp[i];
            v += (f.x + f.y) + (f.z + f.w);
        }
        for (int i = (nvec << 2) + tid; i < grid; i += THREADS)
            v += g_partials[i];
        #pragma unroll
        for (int off = 16; off > 0; off >>= 1)
            v += __shfl_down_sync(0xFFFFFFFFu, v, off);
        if ((tid & 31) == 0) wsum[tid >> 5] = v;
        __syncthreads();
        if (tid == 0)
            out[0] = ((wsum[0] + wsum[1]) + (wsum[2] + wsum[3])) * invB;
    }
}

extern "C" void kernel_launch(void* const* d_in, const int* in_sizes, int n_in,
                              void* d_out, int out_size) {
    const float* kps = (const float*)d_in[0];
    const int B = in_sizes[0] / ROW_F;
    const int ntiles = (B + TILE_ROWS - 1) / TILE_ROWS;   // 1024 for B=131072
    const int grid = (ntiles + 1) / 2;                    // 512: each block = 2 tiles

    sep_loss_fused<<<grid, THREADS>>>(kps, B, grid, 1.0f / (float)B,
                                      (float*)d_out);
}